// round 3
// baseline (speedup 1.0000x reference)
#include <cuda_runtime.h>
#include <cuda_bf16.h>
#include <stdint.h>

// PointPillars BEV scatter, inverted into a full-output gather.
//   out(B, C, H, W): out[b,c,y,x] = feat[map[b,y,x], c]  (or 0 if empty)
//
// Grid constants (fixed by the dataset):
#define BEV_H 496
#define BEV_W 432
#define C_CH  64
#define MAXB  8   // scratch sized for up to 8 batches (dataset uses 4)

// Per-call scratch: pillar-index map over the BEV grid. Rebuilt every launch
// (graph replay re-runs all three kernels), so no cross-call state.
__device__ int g_pillar_map[MAXB * BEV_H * BEV_W];

// ---------------------------------------------------------------------------
// Kernel 1: init map to -1 (vectorized int4 stores; n4 = B*H*W/4)
// ---------------------------------------------------------------------------
__global__ void init_map_kernel(int n4) {
    int i = blockIdx.x * blockDim.x + threadIdx.x;
    if (i < n4) {
        reinterpret_cast<int4*>(g_pillar_map)[i] = make_int4(-1, -1, -1, -1);
    }
}

// ---------------------------------------------------------------------------
// Kernel 2: scatter pillar indices into the map. One thread per pillar.
// coords layout: (M, 3) int32 rows [b, y, x]; collision-free by construction.
// ---------------------------------------------------------------------------
__global__ void scatter_map_kernel(const int* __restrict__ coords, int M) {
    int m = blockIdx.x * blockDim.x + threadIdx.x;
    if (m < M) {
        int b = coords[3 * m + 0];
        int y = coords[3 * m + 1];
        int x = coords[3 * m + 2];
        g_pillar_map[(b * BEV_H + y) * BEV_W + x] = m;
    }
}

// ---------------------------------------------------------------------------
// Kernel 3: full-output gather. Each thread writes one float4 of out.
// Linear thread order = (b, c, y, x4) with x fastest, so consecutive blocks
// walk one channel plane: the 3.4 MB map slice for batch b stays hot in L2
// across all 64 channel planes, and the 31 MB feature table is L2-resident.
// Output is written streaming (__stcs) to avoid evicting map/features.
// ---------------------------------------------------------------------------
__global__ void __launch_bounds__(256) gather_out_kernel(
    const float* __restrict__ feat,   // (M, 64)
    float* __restrict__ out,          // (B, 64, H, W)
    int n4)                           // total float4s = B*C*H*W/4
{
    int i = blockIdx.x * blockDim.x + threadIdx.x;
    if (i >= n4) return;

    // Decompose i = (((b*C + c)*H + y)*W4 + x4); all divisors compile-time.
    const int W4  = BEV_W / 4;            // 108
    const int HW4 = BEV_H * W4;           // 53,568  (one channel plane / 4)
    int plane = i / HW4;                  // b*C + c
    int r     = i - plane * HW4;          // y*W4 + x4
    int y     = r / W4;
    int x4    = r - y * W4;
    int b     = plane >> 6;               // / C_CH
    int c     = plane & (C_CH - 1);

    // Coalesced 16B map read (W divisible by 4, map base 16B-aligned).
    int4 m4 = *reinterpret_cast<const int4*>(
        &g_pillar_map[(b * BEV_H + y) * BEV_W + x4 * 4]);

    float4 v;
    v.x = (m4.x >= 0) ? __ldg(&feat[m4.x * C_CH + c]) : 0.0f;
    v.y = (m4.y >= 0) ? __ldg(&feat[m4.y * C_CH + c]) : 0.0f;
    v.z = (m4.z >= 0) ? __ldg(&feat[m4.z * C_CH + c]) : 0.0f;
    v.w = (m4.w >= 0) ? __ldg(&feat[m4.w * C_CH + c]) : 0.0f;

    // Streaming store: full-line coalesced writes, evict-first in L2.
    __stcs(reinterpret_cast<float4*>(out) + i, v);
}

// ---------------------------------------------------------------------------
// Launch
// Inputs (metadata order): [0] voxel_coords (M,3) int32
//                          [1] voxel_features (M,64) float32
//                          [2] batch_size (scalar; B derived from out_size)
// Output: (B, 64, 496, 432) float32
// ---------------------------------------------------------------------------
extern "C" void kernel_launch(void* const* d_in, const int* in_sizes, int n_in,
                              void* d_out, int out_size) {
    const int*   coords = (const int*)d_in[0];
    const float* feat   = (const float*)d_in[1];
    float*       out    = (float*)d_out;

    int M = in_sizes[0] / 3;
    int B = out_size / (C_CH * BEV_H * BEV_W);
    if (B < 1) B = 1;
    if (B > MAXB) B = MAXB;

    int n_map  = B * BEV_H * BEV_W;      // 857,088 for B=4
    int n_map4 = n_map / 4;              // divisible: W % 4 == 0

    init_map_kernel<<<(n_map4 + 255) / 256, 256>>>(n_map4);
    scatter_map_kernel<<<(M + 255) / 256, 256>>>(coords, M);

    int n4 = out_size / 4;               // 13,713,408
    gather_out_kernel<<<(n4 + 255) / 256, 256>>>(feat, out, n4);
}

// round 5
// speedup vs baseline: 1.5000x; 1.5000x over previous
#include <cuda_runtime.h>
#include <cuda_bf16.h>
#include <stdint.h>

// PointPillars BEV scatter as a full-output gather, channel-quad version.
//   out(B, C, H, W): out[b,c,y,x] = feat[map[b,y,x], c]  (or 0 if empty)
//
// Each gather thread handles a 4-cell x 4-channel patch: one int4 map read,
// four LDG.128 feature reads (16B of a pillar row each), four coalesced
// STG.128 stores into four consecutive channel planes.

#define BEV_H 496
#define BEV_W 432
#define C_CH  64
#define HW    (BEV_H * BEV_W)     // 214,272
#define HW4   (HW / 4)            // 53,568
#define MAXB  8

// Per-call scratch map, rebuilt on every launch (graph replays all kernels).
__device__ int g_pillar_map[MAXB * HW];

// ---------------------------------------------------------------------------
// Kernel 1: init map to -1
// ---------------------------------------------------------------------------
__global__ void init_map_kernel(int n4) {
    int i = blockIdx.x * blockDim.x + threadIdx.x;
    if (i < n4) {
        reinterpret_cast<int4*>(g_pillar_map)[i] = make_int4(-1, -1, -1, -1);
    }
}

// ---------------------------------------------------------------------------
// Kernel 2: scatter pillar indices (collision-free coords by construction)
// ---------------------------------------------------------------------------
__global__ void scatter_map_kernel(const int* __restrict__ coords, int M) {
    int m = blockIdx.x * blockDim.x + threadIdx.x;
    if (m < M) {
        int b = coords[3 * m + 0];
        int y = coords[3 * m + 1];
        int x = coords[3 * m + 2];
        g_pillar_map[b * HW + y * BEV_W + x] = m;
    }
}

// ---------------------------------------------------------------------------
// Kernel 3: gather. Thread i -> (b, c4, r):
//   b  = batch, c4 = channel quad (0..15), r = cell quad within plane (0..HW4)
// Writes float4 to planes c = 4*c4 .. 4*c4+3 at flat cells 4r..4r+3.
// ---------------------------------------------------------------------------
__global__ void __launch_bounds__(256) gather_out_kernel(
    const float* __restrict__ feat,   // (M, 64)
    float* __restrict__ out,          // (B, 64, H, W)
    int n16)                          // out_size / 16
{
    int i = blockIdx.x * blockDim.x + threadIdx.x;
    if (i >= n16) return;

    int r     = i % HW4;              // cell quad index in plane
    int t     = i / HW4;              // b*16 + c4
    int c4    = t & 15;
    int b     = t >> 4;

    // Coalesced 16B map read.
    int4 m4 = *reinterpret_cast<const int4*>(&g_pillar_map[b * HW + 4 * r]);

    // Clamp indices so loads are always in-bounds; select 0 afterward.
    int i0 = m4.x < 0 ? 0 : m4.x;
    int i1 = m4.y < 0 ? 0 : m4.y;
    int i2 = m4.z < 0 ? 0 : m4.z;
    int i3 = m4.w < 0 ? 0 : m4.w;

    int cbase = c4 * 4;
    // 16B-aligned reads of 4 consecutive channels of each pillar row.
    float4 f0 = __ldg(reinterpret_cast<const float4*>(&feat[i0 * C_CH + cbase]));
    float4 f1 = __ldg(reinterpret_cast<const float4*>(&feat[i1 * C_CH + cbase]));
    float4 f2 = __ldg(reinterpret_cast<const float4*>(&feat[i2 * C_CH + cbase]));
    float4 f3 = __ldg(reinterpret_cast<const float4*>(&feat[i3 * C_CH + cbase]));

    const float4 z4 = make_float4(0.f, 0.f, 0.f, 0.f);
    if (m4.x < 0) f0 = z4;
    if (m4.y < 0) f1 = z4;
    if (m4.z < 0) f2 = z4;
    if (m4.w < 0) f3 = z4;

    // f0 = channels cbase..cbase+3 of cell0, etc. Output needs per-channel
    // vectors over cells: transpose the 4x4 in registers.
    float4 o0 = make_float4(f0.x, f1.x, f2.x, f3.x);  // channel cbase+0
    float4 o1 = make_float4(f0.y, f1.y, f2.y, f3.y);  // channel cbase+1
    float4 o2 = make_float4(f0.z, f1.z, f2.z, f3.z);  // channel cbase+2
    float4 o3 = make_float4(f0.w, f1.w, f2.w, f3.w);  // channel cbase+3

    // Coalesced streaming stores into 4 channel planes.
    long base = (long)(b * C_CH + cbase) * HW + 4 * r;
    __stcs(reinterpret_cast<float4*>(&out[base + 0L * HW]), o0);
    __stcs(reinterpret_cast<float4*>(&out[base + 1L * HW]), o1);
    __stcs(reinterpret_cast<float4*>(&out[base + 2L * HW]), o2);
    __stcs(reinterpret_cast<float4*>(&out[base + 3L * HW]), o3);
}

// ---------------------------------------------------------------------------
// Launch
// Inputs: [0] voxel_coords (M,3) int32, [1] voxel_features (M,64) f32,
//         [2] batch_size scalar (B derived from out_size instead).
// Output: (B, 64, 496, 432) float32
// ---------------------------------------------------------------------------
extern "C" void kernel_launch(void* const* d_in, const int* in_sizes, int n_in,
                              void* d_out, int out_size) {
    const int*   coords = (const int*)d_in[0];
    const float* feat   = (const float*)d_in[1];
    float*       out    = (float*)d_out;

    int M = in_sizes[0] / 3;
    int B = out_size / (C_CH * HW);
    if (B < 1) B = 1;
    if (B > MAXB) B = MAXB;

    int n_map4 = (B * HW) / 4;           // W % 4 == 0, so exact

    init_map_kernel<<<(n_map4 + 255) / 256, 256>>>(n_map4);
    scatter_map_kernel<<<(M + 255) / 256, 256>>>(coords, M);

    int n16 = out_size / 16;             // 3,428,352 for B=4
    gather_out_kernel<<<(n16 + 255) / 256, 256>>>(feat, out, n16);
}